// round 14
// baseline (speedup 1.0000x reference)
#include <cuda_runtime.h>
#include <cuda_fp16.h>
#include <cstdint>

// Problem shapes (fixed for this dataset instance)
#define T_DIM 8192
#define N_DIM 4096
#define M_DIM 16384

// Scratch (device globals: allocation-free per harness rules)
__device__ __half g_t[(size_t)T_DIM * N_DIM];   // 64 MB  : t = fwht(x*SV)/sqrt(N), fp16
__device__ __half g_W[(size_t)M_DIM * N_DIM];   // 128 MB : W' = SU/sqrtM * H_M W_hat, fp16
__device__ __half g_Wi[(size_t)M_DIM * N_DIM];  // 128 MB : fp16 intermediate (inner-m transformed)

// ---------------------------------------------------------------------------
// PTX helpers (sm_80-era instructions only: legal on plain sm_103)
// ---------------------------------------------------------------------------
__device__ __forceinline__ uint32_t smem_u32(const void* p) {
    uint32_t a;
    asm("{ .reg .u64 t; cvta.to.shared.u64 t, %1; cvt.u32.u64 %0, t; }" : "=r"(a) : "l"(p));
    return a;
}

__device__ __forceinline__ void cp16(uint32_t dst, const void* src) {
    asm volatile("cp.async.cg.shared.global [%0], [%1], 16;" :: "r"(dst), "l"(src) : "memory");
}
#define CP_COMMIT() asm volatile("cp.async.commit_group;" ::: "memory")
#define CP_WAIT(n)  asm volatile("cp.async.wait_group %0;" :: "n"(n) : "memory")

#define LDSM4(r0, r1, r2, r3, addr) \
    asm volatile("ldmatrix.sync.aligned.m8n8.x4.shared.b16 {%0,%1,%2,%3}, [%4];" \
                 : "=r"(r0), "=r"(r1), "=r"(r2), "=r"(r3) : "r"(addr))

#define MMA16816(d, a, b) \
    asm volatile("mma.sync.aligned.m16n8k16.row.col.f32.f16.f16.f32 " \
                 "{%0,%1,%2,%3}, {%4,%5,%6,%7}, {%8,%9}, {%0,%1,%2,%3};" \
                 : "+f"((d)[0]), "+f"((d)[1]), "+f"((d)[2]), "+f"((d)[3]) \
                 : "r"((a)[0]), "r"((a)[1]), "r"((a)[2]), "r"((a)[3]), \
                   "r"((b)[0]), "r"((b)[1]))

// In-register small FWHTs
__device__ __forceinline__ void fwht16(float* v) {
#pragma unroll
    for (int h = 1; h < 16; h <<= 1)
#pragma unroll
        for (int j = 0; j < 16; j++)
            if ((j & h) == 0) { float a = v[j], b = v[j + h]; v[j] = a + b; v[j + h] = a - b; }
}
__device__ __forceinline__ void fwht8(float* v) {
#pragma unroll
    for (int h = 1; h < 8; h <<= 1)
#pragma unroll
        for (int j = 0; j < 8; j++)
            if ((j & h) == 0) { float a = v[j], b = v[j + h]; v[j] = a + b; v[j + h] = a - b; }
}

__device__ __forceinline__ int skew(int i) { return i + (i >> 4); }

// ---------------------------------------------------------------------------
// FWHT-128 over the row index of a 128x32 fp32 smem tile (stride 33).
// radix-4 (h=1), radix-4 (h=4), radix-8 (h=16). 256 threads.
// ---------------------------------------------------------------------------
#define W_COLS 33

__device__ __forceinline__ void fwht128_rows(float* s, int t) {
#pragma unroll
    for (int hh = 0; hh < 2; hh++) {
        const int h = hh ? 4 : 1;
#pragma unroll
        for (int q = 0; q < 4; q++) {
            int id = t + q * 256;                 // 0..1023
            int k = id & 31, g = id >> 5;         // g in 0..31
            int b0 = (g / h) * (4 * h) + (g % h);
            float* p = s + b0 * W_COLS + k;
            float A0 = p[0], B0 = p[h * W_COLS], C0 = p[2 * h * W_COLS], D0 = p[3 * h * W_COLS];
            p[0]               = A0 + B0 + C0 + D0;
            p[h * W_COLS]      = A0 - B0 + C0 - D0;
            p[2 * h * W_COLS]  = A0 + B0 - C0 - D0;
            p[3 * h * W_COLS]  = A0 - B0 - C0 + D0;
        }
        __syncthreads();
    }
#pragma unroll
    for (int q = 0; q < 2; q++) {
        int id = t + q * 256;                     // 0..511
        int k = id & 31, g = id >> 5;             // g in 0..15
        float* p = s + g * W_COLS + k;
        float v[8];
#pragma unroll
        for (int j = 0; j < 8; j++) v[j] = p[j * 16 * W_COLS];
        fwht8(v);
#pragma unroll
        for (int j = 0; j < 8; j++) p[j * 16 * W_COLS] = v[j];
    }
    __syncthreads();
}

// ---------------------------------------------------------------------------
// K1 dispatcher: blocks [0, 16384) = fused decode + inner-m FWHT-128 on a
// 128x32 tile; blocks [16384, 24576) = fwht_x rows. Register-capped to 42
// (6 CTAs/SM -> 75% occ) since both halves are latency-bound.
// ---------------------------------------------------------------------------
__global__ void __launch_bounds__(256, 6)
k1_dispatch(const int* __restrict__ Q1, const int* __restrict__ Q2,
            const float* __restrict__ cb1, const float* __restrict__ cb2,
            const float* __restrict__ irs_p, __half* __restrict__ Wi,
            const float* __restrict__ x, const float* __restrict__ SV,
            __half* __restrict__ tbuf)
{
    extern __shared__ float s[];
    const int t = threadIdx.x;

    if (blockIdx.x < 16384) {
        // ---- decode + inner-m FWHT-128 on tile (a, kt32) ----
        const int a    = blockIdx.x >> 7;     // outer m-block (0..127)
        const int kt32 = blockIdx.x & 127;    // 32-col tile (0..127)
        const float irs = __ldg(irs_p);

        // batch index loads for both chunks first (raise gather MLP)
        int q1v[2], q2v[2];
#pragma unroll
        for (int q = 0; q < 2; q++) {
            int chunk = t + q * 256;          // 0..511
            int b = chunk >> 2;
            int j = chunk & 3;
            size_t qidx = (size_t)(a * 128 + b) * (N_DIM / 8) + kt32 * 4 + j;
            q1v[q] = __ldg(&Q1[qidx]);
            q2v[q] = __ldg(&Q2[qidx]);
        }
        // decode 128 rows x 4 groups of 8 -> smem (2 chunks/thread)
#pragma unroll
        for (int q = 0; q < 2; q++) {
            int chunk = t + q * 256;
            int b = chunk >> 2;
            int j = chunk & 3;
            const float4* c1 = reinterpret_cast<const float4*>(cb1 + (size_t)q1v[q] * 8);
            const float4* c2 = reinterpret_cast<const float4*>(cb2 + (size_t)q2v[q] * 8);
            float4 a0 = c1[0], a1 = c1[1];
            float4 b0 = c2[0], b1 = c2[1];
            float* sp = s + b * W_COLS + j * 8;
            sp[0] = a0.x + irs * b0.x;  sp[1] = a0.y + irs * b0.y;
            sp[2] = a0.z + irs * b0.z;  sp[3] = a0.w + irs * b0.w;
            sp[4] = a1.x + irs * b1.x;  sp[5] = a1.y + irs * b1.y;
            sp[6] = a1.z + irs * b1.z;  sp[7] = a1.w + irs * b1.w;
        }
        __syncthreads();

        fwht128_rows(s, t);

        __half* ob = Wi + ((size_t)a * 128) * N_DIM + kt32 * 32;
#pragma unroll
        for (int q = 0; q < 2; q++) {
            int chunk = t + q * 256;          // 0..511
            int b = chunk >> 2;
            int c8 = (chunk & 3) * 8;
            float* sp = s + b * W_COLS + c8;
            __half2 h0 = __floats2half2_rn(sp[0], sp[1]);
            __half2 h1 = __floats2half2_rn(sp[2], sp[3]);
            __half2 h2 = __floats2half2_rn(sp[4], sp[5]);
            __half2 h3 = __floats2half2_rn(sp[6], sp[7]);
            uint4 u;
            u.x = *reinterpret_cast<unsigned*>(&h0);
            u.y = *reinterpret_cast<unsigned*>(&h1);
            u.z = *reinterpret_cast<unsigned*>(&h2);
            u.w = *reinterpret_cast<unsigned*>(&h3);
            *reinterpret_cast<uint4*>(ob + (size_t)b * N_DIM + c8) = u;
        }
    } else {
        // ---- fwht_x on row (blockIdx.x - 16384) ----
        const int g = t;
        const int row = blockIdx.x - 16384;
        const float* xr = x + (size_t)row * N_DIM;
        float v[16];

#pragma unroll
        for (int j = 0; j < 16; j++) {
            int e = g + 256 * j;
            v[j] = xr[e] * SV[e];
        }
        fwht16(v);
#pragma unroll
        for (int j = 0; j < 16; j++) s[skew(g + 256 * j)] = v[j];
        __syncthreads();

        {
            int base = (g & 15) + (g >> 4) * 256;
#pragma unroll
            for (int j = 0; j < 16; j++) v[j] = s[skew(base + 16 * j)];
            fwht16(v);
#pragma unroll
            for (int j = 0; j < 16; j++) s[skew(base + 16 * j)] = v[j];
        }
        __syncthreads();

        {
            const float sc = 1.0f / sqrtf((float)N_DIM);
#pragma unroll
            for (int j = 0; j < 16; j++) v[j] = s[skew(16 * g + j)];
            fwht16(v);
            __half2 h[8];
#pragma unroll
            for (int j = 0; j < 8; j++)
                h[j] = __floats2half2_rn(v[2 * j] * sc, v[2 * j + 1] * sc);
            uint4* dst = reinterpret_cast<uint4*>(tbuf + (size_t)row * N_DIM + 16 * g);
            dst[0] = *reinterpret_cast<uint4*>(&h[0]);
            dst[1] = *reinterpret_cast<uint4*>(&h[4]);
        }
    }
}

// ---------------------------------------------------------------------------
// K2: W-transform pass 2 on 128x32 tiles: FWHT-128 over OUTER m-index a,
//     scale by SU[m]/sqrt(M), write fp16 W'. Register-capped like K1.
// ---------------------------------------------------------------------------
__global__ void __launch_bounds__(256, 6)
hadW_pass2(const __half* __restrict__ in, const float* __restrict__ SU,
           __half* __restrict__ W)
{
    extern __shared__ float s[];
    const int b    = blockIdx.x >> 7;     // inner m-index (0..127)
    const int kt32 = blockIdx.x & 127;    // 32-col tile (0..127)
    const int t    = threadIdx.x;

    const __half* base = in + (size_t)b * N_DIM + (size_t)kt32 * 32;
#pragma unroll
    for (int q = 0; q < 2; q++) {
        int chunk = t + q * 256;          // 0..511
        int a = chunk >> 2;               // outer index = smem row
        int c8 = (chunk & 3) * 8;
        uint4 u = *reinterpret_cast<const uint4*>(base + (size_t)a * 128 * N_DIM + c8);
        const __half2* hp = reinterpret_cast<const __half2*>(&u);
        float* sp = s + a * W_COLS + c8;
#pragma unroll
        for (int j = 0; j < 4; j++) {
            float2 f = __half22float2(hp[j]);
            sp[2 * j] = f.x; sp[2 * j + 1] = f.y;
        }
    }
    __syncthreads();

    fwht128_rows(s, t);

    const float inv_m = 1.0f / 128.0f;    // 1/sqrt(16384)
    __half* ob = W + (size_t)b * N_DIM + (size_t)kt32 * 32;
#pragma unroll
    for (int q = 0; q < 2; q++) {
        int chunk = t + q * 256;          // 0..511
        int a = chunk >> 2;
        int c8 = (chunk & 3) * 8;
        float sc = __ldg(&SU[a * 128 + b]) * inv_m;
        float* sp = s + a * W_COLS + c8;
        __half2 h0 = __floats2half2_rn(sp[0] * sc, sp[1] * sc);
        __half2 h1 = __floats2half2_rn(sp[2] * sc, sp[3] * sc);
        __half2 h2 = __floats2half2_rn(sp[4] * sc, sp[5] * sc);
        __half2 h3 = __floats2half2_rn(sp[6] * sc, sp[7] * sc);
        uint4 u;
        u.x = *reinterpret_cast<unsigned*>(&h0);
        u.y = *reinterpret_cast<unsigned*>(&h1);
        u.z = *reinterpret_cast<unsigned*>(&h2);
        u.w = *reinterpret_cast<unsigned*>(&h3);
        *reinterpret_cast<uint4*>(ob + (size_t)a * 128 * N_DIM + c8) = u;
    }
}

// ---------------------------------------------------------------------------
// K3: GEMM y[T,M] = (t @ W'^T) * Wscale, fp32 out. Block 128x128x64,
//     warp tile 64x32, 3-stage cp.async (96 KB smem -> 2 CTAs/SM).
//     (Proven R10/R13 configuration — at the mma.sync ceiling; unchanged.)
// ---------------------------------------------------------------------------
#define BM 128
#define BN 128
#define BK 64
#define STAGES 3
#define NKC (N_DIM / BK)   // 64

__global__ void __launch_bounds__(256, 2)
gemm_mma_kernel(const __half* __restrict__ A, const __half* __restrict__ B,
                float* __restrict__ C, const float* __restrict__ Wscale_p)
{
    extern __shared__ uint4 smem4[];
    const uint32_t sbase = smem_u32(smem4);

    const int tid = threadIdx.x;
    const int wid = tid >> 5;
    const int lane = tid & 31;
    const int bm = blockIdx.x * BM;   // T dimension (A L2-resident)
    const int bn = blockIdx.y * BN;   // M dimension

    const int wm = (wid >> 2) * 64;
    const int wn = (wid & 3) * 32;

    float acc[4][4][4];
#pragma unroll
    for (int i = 0; i < 4; i++)
#pragma unroll
        for (int j = 0; j < 4; j++)
#pragma unroll
            for (int q = 0; q < 4; q++) acc[i][j][q] = 0.0f;

    const int lrow = tid >> 3;
    const int lc = tid & 7;
    const __half* Ab = A + (size_t)bm * N_DIM + lc * 8;
    const __half* Bb = B + (size_t)bn * N_DIM + lc * 8;

    auto issue_stage = [&](int kc) {
        int st = kc % STAGES;
        const __half* Ag = Ab + kc * BK;
        const __half* Bg = Bb + kc * BK;
#pragma unroll
        for (int p = 0; p < 4; p++) {
            int r = lrow + p * 32;
            int cc = lc ^ (r & 7);
            uint32_t da = sbase + ((st * 1024 + r * 8 + cc) << 4);
            uint32_t db = sbase + (((STAGES + st) * 1024 + r * 8 + cc) << 4);
            cp16(da, Ag + (size_t)r * N_DIM);
            cp16(db, Bg + (size_t)r * N_DIM);
        }
        CP_COMMIT();
    };

    issue_stage(0);
    issue_stage(1);

    const int ra = wm + (lane & 15);
    const int ca = (lane >> 4);
    const int rb = wn + (lane & 7) + ((lane & 16) ? 8 : 0);
    const int cb = (lane >> 3) & 1;

    for (int kc = 0; kc < NKC; kc++) {
        CP_WAIT(1);
        __syncthreads();

        if (kc + 2 < NKC) issue_stage(kc + 2);
        else CP_COMMIT();

        const int st = kc % STAGES;
        const uint32_t abase = sbase + ((st * 1024) << 4);
        const uint32_t bbase = sbase + (((STAGES + st) * 1024) << 4);

#pragma unroll
        for (int kk = 0; kk < 4; kk++) {
            uint32_t a[4][4];
            uint32_t b[4][2];
#pragma unroll
            for (int mi = 0; mi < 4; mi++) {
                int r = ra + mi * 16;
                int c = (kk * 2 + ca) ^ (r & 7);
                LDSM4(a[mi][0], a[mi][1], a[mi][2], a[mi][3],
                      abase + ((r * 8 + c) << 4));
            }
#pragma unroll
            for (int njp = 0; njp < 2; njp++) {
                int r = rb + njp * 16;
                int c = (kk * 2 + cb) ^ (r & 7);
                uint32_t t0, t1, t2, t3;
                LDSM4(t0, t1, t2, t3, bbase + ((r * 8 + c) << 4));
                b[njp * 2 + 0][0] = t0;  b[njp * 2 + 0][1] = t1;
                b[njp * 2 + 1][0] = t2;  b[njp * 2 + 1][1] = t3;
            }
#pragma unroll
            for (int mi = 0; mi < 4; mi++)
#pragma unroll
                for (int nj = 0; nj < 4; nj++)
                    MMA16816(acc[mi][nj], a[mi], b[nj]);
        }
    }

    // epilogue: fp32 stores scaled by Wscale
    const float ws = __ldg(Wscale_p);
    const int er = lane >> 2;
    const int ec = (lane & 3) * 2;
#pragma unroll
    for (int mi = 0; mi < 4; mi++) {
#pragma unroll
        for (int nj = 0; nj < 4; nj++) {
            size_t r0 = (size_t)(bm + wm + mi * 16 + er) * M_DIM + (bn + wn + nj * 8 + ec);
            size_t r1 = r0 + (size_t)8 * M_DIM;
            __stcs(reinterpret_cast<float2*>(C + r0),
                   make_float2(acc[mi][nj][0] * ws, acc[mi][nj][1] * ws));
            __stcs(reinterpret_cast<float2*>(C + r1),
                   make_float2(acc[mi][nj][2] * ws, acc[mi][nj][3] * ws));
        }
    }
}

// ---------------------------------------------------------------------------
// Launch
// ---------------------------------------------------------------------------
extern "C" void kernel_launch(void* const* d_in, const int* in_sizes, int n_in,
                              void* d_out, int out_size)
{
    const float* x   = (const float*)d_in[0];
    const int*   Q1  = (const int*)d_in[1];
    const int*   Q2  = (const int*)d_in[2];
    const float* SU  = (const float*)d_in[3];
    const float* SV  = (const float*)d_in[4];
    const float* cb1 = (const float*)d_in[5];
    const float* cb2 = (const float*)d_in[6];
    const float* Wsc = (const float*)d_in[7];
    const float* irs = (const float*)d_in[8];
    float* out = (float*)d_out;

    __half *t_p, *W_p, *Wi_p;
    cudaGetSymbolAddress((void**)&t_p, g_t);
    cudaGetSymbolAddress((void**)&W_p, g_W);
    cudaGetSymbolAddress((void**)&Wi_p, g_Wi);

    // K1: fused [decode + inner-m FWHT tiles] + [fwht_x rows]
    // smem = max(128*33*4 = 16.9 KB, fwht_x (4096+256)*4 = 17.4 KB)
    int psmem = (4096 + 256) * (int)sizeof(float);
    cudaFuncSetAttribute(k1_dispatch, cudaFuncAttributeMaxDynamicSharedMemorySize, psmem);
    cudaFuncSetAttribute(hadW_pass2, cudaFuncAttributeMaxDynamicSharedMemorySize, psmem);
    k1_dispatch<<<16384 + 8192, 256, psmem>>>(Q1, Q2, cb1, cb2, irs, Wi_p, x, SV, t_p);

    // K2: outer-m FWHT + SU scale (128x32 tiles)
    hadW_pass2<<<16384, 256, 128 * W_COLS * (int)sizeof(float)>>>(Wi_p, SU, W_p);

    // K3: GEMM directly into d_out (fp32, scaled by Wscale) — proven config
    int gemm_smem = 2 * STAGES * 128 * 8 * (int)sizeof(uint4);
    cudaFuncSetAttribute(gemm_mma_kernel,
                         cudaFuncAttributeMaxDynamicSharedMemorySize, gemm_smem);
    dim3 grid(T_DIM / BM, M_DIM / BN);
    gemm_mma_kernel<<<grid, 256, gemm_smem>>>(t_p, W_p, out, Wsc);
}

// round 15
// speedup vs baseline: 1.0387x; 1.0387x over previous
#include <cuda_runtime.h>
#include <cuda_fp16.h>
#include <cstdint>

// Problem shapes (fixed for this dataset instance)
#define T_DIM 8192
#define N_DIM 4096
#define M_DIM 16384

// Scratch (device globals: allocation-free per harness rules)
__device__ __half g_t[(size_t)T_DIM * N_DIM];   // 64 MB  : t = fwht(x*SV)/sqrt(N), fp16
__device__ __half g_W[(size_t)M_DIM * N_DIM];   // 128 MB : W' = SU/sqrtM * H_M W_hat, fp16
__device__ __half g_Wi[(size_t)M_DIM * N_DIM];  // 128 MB : fp16 intermediate (inner-m transformed)

// ---------------------------------------------------------------------------
// PTX helpers (sm_80-era instructions only: legal on plain sm_103)
// ---------------------------------------------------------------------------
__device__ __forceinline__ uint32_t smem_u32(const void* p) {
    uint32_t a;
    asm("{ .reg .u64 t; cvta.to.shared.u64 t, %1; cvt.u32.u64 %0, t; }" : "=r"(a) : "l"(p));
    return a;
}

__device__ __forceinline__ void cp16(uint32_t dst, const void* src) {
    asm volatile("cp.async.cg.shared.global [%0], [%1], 16;" :: "r"(dst), "l"(src) : "memory");
}
#define CP_COMMIT() asm volatile("cp.async.commit_group;" ::: "memory")
#define CP_WAIT(n)  asm volatile("cp.async.wait_group %0;" :: "n"(n) : "memory")

#define LDSM4(r0, r1, r2, r3, addr) \
    asm volatile("ldmatrix.sync.aligned.m8n8.x4.shared.b16 {%0,%1,%2,%3}, [%4];" \
                 : "=r"(r0), "=r"(r1), "=r"(r2), "=r"(r3) : "r"(addr))

#define MMA16816(d, a, b) \
    asm volatile("mma.sync.aligned.m16n8k16.row.col.f32.f16.f16.f32 " \
                 "{%0,%1,%2,%3}, {%4,%5,%6,%7}, {%8,%9}, {%0,%1,%2,%3};" \
                 : "+f"((d)[0]), "+f"((d)[1]), "+f"((d)[2]), "+f"((d)[3]) \
                 : "r"((a)[0]), "r"((a)[1]), "r"((a)[2]), "r"((a)[3]), \
                   "r"((b)[0]), "r"((b)[1]))

// In-register small FWHTs
__device__ __forceinline__ void fwht16(float* v) {
#pragma unroll
    for (int h = 1; h < 16; h <<= 1)
#pragma unroll
        for (int j = 0; j < 16; j++)
            if ((j & h) == 0) { float a = v[j], b = v[j + h]; v[j] = a + b; v[j + h] = a - b; }
}
__device__ __forceinline__ void fwht8(float* v) {
#pragma unroll
    for (int h = 1; h < 8; h <<= 1)
#pragma unroll
        for (int j = 0; j < 8; j++)
            if ((j & h) == 0) { float a = v[j], b = v[j + h]; v[j] = a + b; v[j + h] = a - b; }
}

__device__ __forceinline__ int skew(int i) { return i + (i >> 4); }

// ---------------------------------------------------------------------------
// FWHT-128 over the row index of a 128x32 fp32 smem tile (stride 33).
// radix-4 (h=1), radix-4 (h=4), radix-8 (h=16). 256 threads.
// ---------------------------------------------------------------------------
#define W_COLS 33

__device__ __forceinline__ void fwht128_rows(float* s, int t) {
#pragma unroll
    for (int hh = 0; hh < 2; hh++) {
        const int h = hh ? 4 : 1;
#pragma unroll
        for (int q = 0; q < 4; q++) {
            int id = t + q * 256;                 // 0..1023
            int k = id & 31, g = id >> 5;         // g in 0..31
            int b0 = (g / h) * (4 * h) + (g % h);
            float* p = s + b0 * W_COLS + k;
            float A0 = p[0], B0 = p[h * W_COLS], C0 = p[2 * h * W_COLS], D0 = p[3 * h * W_COLS];
            p[0]               = A0 + B0 + C0 + D0;
            p[h * W_COLS]      = A0 - B0 + C0 - D0;
            p[2 * h * W_COLS]  = A0 + B0 - C0 - D0;
            p[3 * h * W_COLS]  = A0 - B0 - C0 + D0;
        }
        __syncthreads();
    }
#pragma unroll
    for (int q = 0; q < 2; q++) {
        int id = t + q * 256;                     // 0..511
        int k = id & 31, g = id >> 5;             // g in 0..15
        float* p = s + g * W_COLS + k;
        float v[8];
#pragma unroll
        for (int j = 0; j < 8; j++) v[j] = p[j * 16 * W_COLS];
        fwht8(v);
#pragma unroll
        for (int j = 0; j < 8; j++) p[j * 16 * W_COLS] = v[j];
    }
    __syncthreads();
}

// ---------------------------------------------------------------------------
// K1 dispatcher: blocks [0, 16384) = fused decode + inner-m FWHT-128 on a
// 128x32 tile; blocks [16384, 24576) = fwht_x rows. (R13 configuration —
// decode half is L1tex-wavefront-bound; occupancy tuning proven neutral.)
// ---------------------------------------------------------------------------
__global__ void __launch_bounds__(256)
k1_dispatch(const int* __restrict__ Q1, const int* __restrict__ Q2,
            const float* __restrict__ cb1, const float* __restrict__ cb2,
            const float* __restrict__ irs_p, __half* __restrict__ Wi,
            const float* __restrict__ x, const float* __restrict__ SV,
            __half* __restrict__ tbuf)
{
    extern __shared__ float s[];
    const int t = threadIdx.x;

    if (blockIdx.x < 16384) {
        // ---- decode + inner-m FWHT-128 on tile (a, kt32) ----
        const int a    = blockIdx.x >> 7;     // outer m-block (0..127)
        const int kt32 = blockIdx.x & 127;    // 32-col tile (0..127)
        const float irs = __ldg(irs_p);

#pragma unroll
        for (int q = 0; q < 2; q++) {
            int chunk = t + q * 256;          // 0..511
            int b = chunk >> 2;               // row in tile
            int j = chunk & 3;                // 8-col group within tile
            size_t qidx = (size_t)(a * 128 + b) * (N_DIM / 8) + kt32 * 4 + j;
            int q1 = __ldg(&Q1[qidx]);
            int q2 = __ldg(&Q2[qidx]);
            const float4* c1 = reinterpret_cast<const float4*>(cb1 + (size_t)q1 * 8);
            const float4* c2 = reinterpret_cast<const float4*>(cb2 + (size_t)q2 * 8);
            float4 a0 = c1[0], a1 = c1[1];
            float4 b0 = c2[0], b1 = c2[1];
            float* sp = s + b * W_COLS + j * 8;
            sp[0] = a0.x + irs * b0.x;  sp[1] = a0.y + irs * b0.y;
            sp[2] = a0.z + irs * b0.z;  sp[3] = a0.w + irs * b0.w;
            sp[4] = a1.x + irs * b1.x;  sp[5] = a1.y + irs * b1.y;
            sp[6] = a1.z + irs * b1.z;  sp[7] = a1.w + irs * b1.w;
        }
        __syncthreads();

        fwht128_rows(s, t);

        __half* ob = Wi + ((size_t)a * 128) * N_DIM + kt32 * 32;
#pragma unroll
        for (int q = 0; q < 2; q++) {
            int chunk = t + q * 256;          // 0..511
            int b = chunk >> 2;
            int c8 = (chunk & 3) * 8;
            float* sp = s + b * W_COLS + c8;
            __half2 h0 = __floats2half2_rn(sp[0], sp[1]);
            __half2 h1 = __floats2half2_rn(sp[2], sp[3]);
            __half2 h2 = __floats2half2_rn(sp[4], sp[5]);
            __half2 h3 = __floats2half2_rn(sp[6], sp[7]);
            uint4 u;
            u.x = *reinterpret_cast<unsigned*>(&h0);
            u.y = *reinterpret_cast<unsigned*>(&h1);
            u.z = *reinterpret_cast<unsigned*>(&h2);
            u.w = *reinterpret_cast<unsigned*>(&h3);
            *reinterpret_cast<uint4*>(ob + (size_t)b * N_DIM + c8) = u;
        }
    } else {
        // ---- fwht_x on row (blockIdx.x - 16384) ----
        const int g = t;
        const int row = blockIdx.x - 16384;
        const float* xr = x + (size_t)row * N_DIM;
        float v[16];

#pragma unroll
        for (int j = 0; j < 16; j++) {
            int e = g + 256 * j;
            v[j] = xr[e] * SV[e];
        }
        fwht16(v);
#pragma unroll
        for (int j = 0; j < 16; j++) s[skew(g + 256 * j)] = v[j];
        __syncthreads();

        {
            int base = (g & 15) + (g >> 4) * 256;
#pragma unroll
            for (int j = 0; j < 16; j++) v[j] = s[skew(base + 16 * j)];
            fwht16(v);
#pragma unroll
            for (int j = 0; j < 16; j++) s[skew(base + 16 * j)] = v[j];
        }
        __syncthreads();

        {
            const float sc = 1.0f / sqrtf((float)N_DIM);
#pragma unroll
            for (int j = 0; j < 16; j++) v[j] = s[skew(16 * g + j)];
            fwht16(v);
            __half2 h[8];
#pragma unroll
            for (int j = 0; j < 8; j++)
                h[j] = __floats2half2_rn(v[2 * j] * sc, v[2 * j + 1] * sc);
            uint4* dst = reinterpret_cast<uint4*>(tbuf + (size_t)row * N_DIM + 16 * g);
            dst[0] = *reinterpret_cast<uint4*>(&h[0]);
            dst[1] = *reinterpret_cast<uint4*>(&h[4]);
        }
    }
}

// ---------------------------------------------------------------------------
// K2: W-transform pass 2 on 128x32 tiles: FWHT-128 over OUTER m-index a,
//     scale by SU[m]/sqrt(M), write fp16 W'.
// ---------------------------------------------------------------------------
__global__ void __launch_bounds__(256)
hadW_pass2(const __half* __restrict__ in, const float* __restrict__ SU,
           __half* __restrict__ W)
{
    extern __shared__ float s[];
    const int b    = blockIdx.x >> 7;     // inner m-index (0..127)
    const int kt32 = blockIdx.x & 127;    // 32-col tile (0..127)
    const int t    = threadIdx.x;

    const __half* base = in + (size_t)b * N_DIM + (size_t)kt32 * 32;
#pragma unroll
    for (int q = 0; q < 2; q++) {
        int chunk = t + q * 256;          // 0..511
        int a = chunk >> 2;               // outer index = smem row
        int c8 = (chunk & 3) * 8;
        uint4 u = *reinterpret_cast<const uint4*>(base + (size_t)a * 128 * N_DIM + c8);
        const __half2* hp = reinterpret_cast<const __half2*>(&u);
        float* sp = s + a * W_COLS + c8;
#pragma unroll
        for (int j = 0; j < 4; j++) {
            float2 f = __half22float2(hp[j]);
            sp[2 * j] = f.x; sp[2 * j + 1] = f.y;
        }
    }
    __syncthreads();

    fwht128_rows(s, t);

    const float inv_m = 1.0f / 128.0f;    // 1/sqrt(16384)
    __half* ob = W + (size_t)b * N_DIM + (size_t)kt32 * 32;
#pragma unroll
    for (int q = 0; q < 2; q++) {
        int chunk = t + q * 256;          // 0..511
        int a = chunk >> 2;
        int c8 = (chunk & 3) * 8;
        float sc = __ldg(&SU[a * 128 + b]) * inv_m;
        float* sp = s + a * W_COLS + c8;
        __half2 h0 = __floats2half2_rn(sp[0] * sc, sp[1] * sc);
        __half2 h1 = __floats2half2_rn(sp[2] * sc, sp[3] * sc);
        __half2 h2 = __floats2half2_rn(sp[4] * sc, sp[5] * sc);
        __half2 h3 = __floats2half2_rn(sp[6] * sc, sp[7] * sc);
        uint4 u;
        u.x = *reinterpret_cast<unsigned*>(&h0);
        u.y = *reinterpret_cast<unsigned*>(&h1);
        u.z = *reinterpret_cast<unsigned*>(&h2);
        u.w = *reinterpret_cast<unsigned*>(&h3);
        *reinterpret_cast<uint4*>(ob + (size_t)a * 128 * N_DIM + c8) = u;
    }
}

// ---------------------------------------------------------------------------
// K3: GEMM y[T,M] = (t @ W'^T) * Wscale, fp32 out. Block 128x128x64,
//     warp tile 64x32, 3-stage cp.async (96 KB smem -> 2 CTAs/SM).
//     kc mainloop unrolled x3 so stage indices are compile-time constants.
// ---------------------------------------------------------------------------
#define BM 128
#define BN 128
#define BK 64
#define STAGES 3
#define NKC (N_DIM / BK)   // 64

__global__ void __launch_bounds__(256, 2)
gemm_mma_kernel(const __half* __restrict__ A, const __half* __restrict__ B,
                float* __restrict__ C, const float* __restrict__ Wscale_p)
{
    extern __shared__ uint4 smem4[];
    const uint32_t sbase = smem_u32(smem4);

    const int tid = threadIdx.x;
    const int wid = tid >> 5;
    const int lane = tid & 31;
    const int bm = blockIdx.x * BM;   // T dimension (A L2-resident)
    const int bn = blockIdx.y * BN;   // M dimension

    const int wm = (wid >> 2) * 64;
    const int wn = (wid & 3) * 32;

    float acc[4][4][4];
#pragma unroll
    for (int i = 0; i < 4; i++)
#pragma unroll
        for (int j = 0; j < 4; j++)
#pragma unroll
            for (int q = 0; q < 4; q++) acc[i][j][q] = 0.0f;

    const int lrow = tid >> 3;
    const int lc = tid & 7;
    const __half* Ab = A + (size_t)bm * N_DIM + lc * 8;
    const __half* Bb = B + (size_t)bn * N_DIM + lc * 8;

    auto issue_stage = [&](int kc, int st) {
        const __half* Ag = Ab + kc * BK;
        const __half* Bg = Bb + kc * BK;
#pragma unroll
        for (int p = 0; p < 4; p++) {
            int r = lrow + p * 32;
            int cc = lc ^ (r & 7);
            uint32_t da = sbase + ((st * 1024 + r * 8 + cc) << 4);
            uint32_t db = sbase + (((STAGES + st) * 1024 + r * 8 + cc) << 4);
            cp16(da, Ag + (size_t)r * N_DIM);
            cp16(db, Bg + (size_t)r * N_DIM);
        }
        CP_COMMIT();
    };

    issue_stage(0, 0);
    issue_stage(1, 1);

    const int ra = wm + (lane & 15);
    const int ca = (lane >> 4);
    const int rb = wn + (lane & 7) + ((lane & 16) ? 8 : 0);
    const int cb = (lane >> 3) & 1;

#pragma unroll 3
    for (int kc = 0; kc < NKC; kc++) {
        CP_WAIT(1);
        __syncthreads();

        if (kc + 2 < NKC) issue_stage(kc + 2, (kc + 2) % STAGES);
        else CP_COMMIT();

        const int st = kc % STAGES;
        const uint32_t abase = sbase + ((st * 1024) << 4);
        const uint32_t bbase = sbase + (((STAGES + st) * 1024) << 4);

#pragma unroll
        for (int kk = 0; kk < 4; kk++) {
            uint32_t a[4][4];
            uint32_t b[4][2];
#pragma unroll
            for (int mi = 0; mi < 4; mi++) {
                int r = ra + mi * 16;
                int c = (kk * 2 + ca) ^ (r & 7);
                LDSM4(a[mi][0], a[mi][1], a[mi][2], a[mi][3],
                      abase + ((r * 8 + c) << 4));
            }
#pragma unroll
            for (int njp = 0; njp < 2; njp++) {
                int r = rb + njp * 16;
                int c = (kk * 2 + cb) ^ (r & 7);
                uint32_t t0, t1, t2, t3;
                LDSM4(t0, t1, t2, t3, bbase + ((r * 8 + c) << 4));
                b[njp * 2 + 0][0] = t0;  b[njp * 2 + 0][1] = t1;
                b[njp * 2 + 1][0] = t2;  b[njp * 2 + 1][1] = t3;
            }
#pragma unroll
            for (int mi = 0; mi < 4; mi++)
#pragma unroll
                for (int nj = 0; nj < 4; nj++)
                    MMA16816(acc[mi][nj], a[mi], b[nj]);
        }
    }

    // epilogue: fp32 stores scaled by Wscale
    const float ws = __ldg(Wscale_p);
    const int er = lane >> 2;
    const int ec = (lane & 3) * 2;
#pragma unroll
    for (int mi = 0; mi < 4; mi++) {
#pragma unroll
        for (int nj = 0; nj < 4; nj++) {
            size_t r0 = (size_t)(bm + wm + mi * 16 + er) * M_DIM + (bn + wn + nj * 8 + ec);
            size_t r1 = r0 + (size_t)8 * M_DIM;
            __stcs(reinterpret_cast<float2*>(C + r0),
                   make_float2(acc[mi][nj][0] * ws, acc[mi][nj][1] * ws));
            __stcs(reinterpret_cast<float2*>(C + r1),
                   make_float2(acc[mi][nj][2] * ws, acc[mi][nj][3] * ws));
        }
    }
}

// ---------------------------------------------------------------------------
// Launch
// ---------------------------------------------------------------------------
extern "C" void kernel_launch(void* const* d_in, const int* in_sizes, int n_in,
                              void* d_out, int out_size)
{
    const float* x   = (const float*)d_in[0];
    const int*   Q1  = (const int*)d_in[1];
    const int*   Q2  = (const int*)d_in[2];
    const float* SU  = (const float*)d_in[3];
    const float* SV  = (const float*)d_in[4];
    const float* cb1 = (const float*)d_in[5];
    const float* cb2 = (const float*)d_in[6];
    const float* Wsc = (const float*)d_in[7];
    const float* irs = (const float*)d_in[8];
    float* out = (float*)d_out;

    __half *t_p, *W_p, *Wi_p;
    cudaGetSymbolAddress((void**)&t_p, g_t);
    cudaGetSymbolAddress((void**)&W_p, g_W);
    cudaGetSymbolAddress((void**)&Wi_p, g_Wi);

    // K1: fused [decode + inner-m FWHT tiles] + [fwht_x rows]
    int psmem = (4096 + 256) * (int)sizeof(float);
    cudaFuncSetAttribute(k1_dispatch, cudaFuncAttributeMaxDynamicSharedMemorySize, psmem);
    cudaFuncSetAttribute(hadW_pass2, cudaFuncAttributeMaxDynamicSharedMemorySize, psmem);
    k1_dispatch<<<16384 + 8192, 256, psmem>>>(Q1, Q2, cb1, cb2, irs, Wi_p, x, SV, t_p);

    // K2: outer-m FWHT + SU scale (128x32 tiles)
    hadW_pass2<<<16384, 256, 128 * W_COLS * (int)sizeof(float)>>>(Wi_p, SU, W_p);

    // K3: GEMM directly into d_out (fp32, scaled by Wscale)
    int gemm_smem = 2 * STAGES * 128 * 8 * (int)sizeof(uint4);
    cudaFuncSetAttribute(gemm_mma_kernel,
                         cudaFuncAttributeMaxDynamicSharedMemorySize, gemm_smem);
    dim3 grid(T_DIM / BM, M_DIM / BN);
    gemm_mma_kernel<<<grid, 256, gemm_smem>>>(t_p, W_p, out, Wsc);
}

// round 16
// speedup vs baseline: 1.0388x; 1.0001x over previous
#include <cuda_runtime.h>
#include <cuda_fp16.h>
#include <cstdint>

// Problem shapes (fixed for this dataset instance)
#define T_DIM 8192
#define N_DIM 4096
#define M_DIM 16384

// Scratch (device globals: allocation-free per harness rules)
__device__ __half g_t[(size_t)T_DIM * N_DIM];   // 64 MB  : t = fwht(x*SV)/sqrt(N), fp16
__device__ __half g_W[(size_t)M_DIM * N_DIM];   // 128 MB : W' = SU/sqrtM * H_M W_hat, fp16
__device__ __half g_Wi[(size_t)M_DIM * N_DIM];  // 128 MB : fp16 intermediate (inner-m transformed)

// ---------------------------------------------------------------------------
// PTX helpers (sm_80-era instructions only: legal on plain sm_103)
// ---------------------------------------------------------------------------
__device__ __forceinline__ uint32_t smem_u32(const void* p) {
    uint32_t a;
    asm("{ .reg .u64 t; cvta.to.shared.u64 t, %1; cvt.u32.u64 %0, t; }" : "=r"(a) : "l"(p));
    return a;
}

__device__ __forceinline__ void cp16(uint32_t dst, const void* src) {
    asm volatile("cp.async.cg.shared.global [%0], [%1], 16;" :: "r"(dst), "l"(src) : "memory");
}
#define CP_COMMIT() asm volatile("cp.async.commit_group;" ::: "memory")
#define CP_WAIT(n)  asm volatile("cp.async.wait_group %0;" :: "n"(n) : "memory")

#define LDSM4(r0, r1, r2, r3, addr) \
    asm volatile("ldmatrix.sync.aligned.m8n8.x4.shared.b16 {%0,%1,%2,%3}, [%4];" \
                 : "=r"(r0), "=r"(r1), "=r"(r2), "=r"(r3) : "r"(addr))

#define MMA16816(d, a, b) \
    asm volatile("mma.sync.aligned.m16n8k16.row.col.f32.f16.f16.f32 " \
                 "{%0,%1,%2,%3}, {%4,%5,%6,%7}, {%8,%9}, {%0,%1,%2,%3};" \
                 : "+f"((d)[0]), "+f"((d)[1]), "+f"((d)[2]), "+f"((d)[3]) \
                 : "r"((a)[0]), "r"((a)[1]), "r"((a)[2]), "r"((a)[3]), \
                   "r"((b)[0]), "r"((b)[1]))

// In-register small FWHTs
__device__ __forceinline__ void fwht16(float* v) {
#pragma unroll
    for (int h = 1; h < 16; h <<= 1)
#pragma unroll
        for (int j = 0; j < 16; j++)
            if ((j & h) == 0) { float a = v[j], b = v[j + h]; v[j] = a + b; v[j + h] = a - b; }
}
__device__ __forceinline__ void fwht8(float* v) {
#pragma unroll
    for (int h = 1; h < 8; h <<= 1)
#pragma unroll
        for (int j = 0; j < 8; j++)
            if ((j & h) == 0) { float a = v[j], b = v[j + h]; v[j] = a + b; v[j + h] = a - b; }
}

__device__ __forceinline__ int skew(int i) { return i + (i >> 4); }

// ---------------------------------------------------------------------------
// FWHT-128 over the row index of a 128x32 fp32 smem tile (stride 33).
// radix-4 (h=1), radix-4 (h=4), radix-8 (h=16). 256 threads.
// ---------------------------------------------------------------------------
#define W_COLS 33

__device__ __forceinline__ void fwht128_rows(float* s, int t) {
#pragma unroll
    for (int hh = 0; hh < 2; hh++) {
        const int h = hh ? 4 : 1;
#pragma unroll
        for (int q = 0; q < 4; q++) {
            int id = t + q * 256;                 // 0..1023
            int k = id & 31, g = id >> 5;         // g in 0..31
            int b0 = (g / h) * (4 * h) + (g % h);
            float* p = s + b0 * W_COLS + k;
            float A0 = p[0], B0 = p[h * W_COLS], C0 = p[2 * h * W_COLS], D0 = p[3 * h * W_COLS];
            p[0]               = A0 + B0 + C0 + D0;
            p[h * W_COLS]      = A0 - B0 + C0 - D0;
            p[2 * h * W_COLS]  = A0 + B0 - C0 - D0;
            p[3 * h * W_COLS]  = A0 - B0 - C0 + D0;
        }
        __syncthreads();
    }
#pragma unroll
    for (int q = 0; q < 2; q++) {
        int id = t + q * 256;                     // 0..511
        int k = id & 31, g = id >> 5;             // g in 0..15
        float* p = s + g * W_COLS + k;
        float v[8];
#pragma unroll
        for (int j = 0; j < 8; j++) v[j] = p[j * 16 * W_COLS];
        fwht8(v);
#pragma unroll
        for (int j = 0; j < 8; j++) p[j * 16 * W_COLS] = v[j];
    }
    __syncthreads();
}

// ---------------------------------------------------------------------------
// K1 dispatcher: blocks [0, 16384) = fused decode + inner-m FWHT-128 on a
// 128x32 tile; blocks [16384, 24576) = fwht_x rows. (R13 configuration —
// decode half is L1tex-wavefront-bound; occupancy tuning proven neutral.)
// ---------------------------------------------------------------------------
__global__ void __launch_bounds__(256)
k1_dispatch(const int* __restrict__ Q1, const int* __restrict__ Q2,
            const float* __restrict__ cb1, const float* __restrict__ cb2,
            const float* __restrict__ irs_p, __half* __restrict__ Wi,
            const float* __restrict__ x, const float* __restrict__ SV,
            __half* __restrict__ tbuf)
{
    extern __shared__ float s[];
    const int t = threadIdx.x;

    if (blockIdx.x < 16384) {
        // ---- decode + inner-m FWHT-128 on tile (a, kt32) ----
        const int a    = blockIdx.x >> 7;     // outer m-block (0..127)
        const int kt32 = blockIdx.x & 127;    // 32-col tile (0..127)
        const float irs = __ldg(irs_p);

#pragma unroll
        for (int q = 0; q < 2; q++) {
            int chunk = t + q * 256;          // 0..511
            int b = chunk >> 2;               // row in tile
            int j = chunk & 3;                // 8-col group within tile
            size_t qidx = (size_t)(a * 128 + b) * (N_DIM / 8) + kt32 * 4 + j;
            int q1 = __ldg(&Q1[qidx]);
            int q2 = __ldg(&Q2[qidx]);
            const float4* c1 = reinterpret_cast<const float4*>(cb1 + (size_t)q1 * 8);
            const float4* c2 = reinterpret_cast<const float4*>(cb2 + (size_t)q2 * 8);
            float4 a0 = c1[0], a1 = c1[1];
            float4 b0 = c2[0], b1 = c2[1];
            float* sp = s + b * W_COLS + j * 8;
            sp[0] = a0.x + irs * b0.x;  sp[1] = a0.y + irs * b0.y;
            sp[2] = a0.z + irs * b0.z;  sp[3] = a0.w + irs * b0.w;
            sp[4] = a1.x + irs * b1.x;  sp[5] = a1.y + irs * b1.y;
            sp[6] = a1.z + irs * b1.z;  sp[7] = a1.w + irs * b1.w;
        }
        __syncthreads();

        fwht128_rows(s, t);

        __half* ob = Wi + ((size_t)a * 128) * N_DIM + kt32 * 32;
#pragma unroll
        for (int q = 0; q < 2; q++) {
            int chunk = t + q * 256;          // 0..511
            int b = chunk >> 2;
            int c8 = (chunk & 3) * 8;
            float* sp = s + b * W_COLS + c8;
            __half2 h0 = __floats2half2_rn(sp[0], sp[1]);
            __half2 h1 = __floats2half2_rn(sp[2], sp[3]);
            __half2 h2 = __floats2half2_rn(sp[4], sp[5]);
            __half2 h3 = __floats2half2_rn(sp[6], sp[7]);
            uint4 u;
            u.x = *reinterpret_cast<unsigned*>(&h0);
            u.y = *reinterpret_cast<unsigned*>(&h1);
            u.z = *reinterpret_cast<unsigned*>(&h2);
            u.w = *reinterpret_cast<unsigned*>(&h3);
            *reinterpret_cast<uint4*>(ob + (size_t)b * N_DIM + c8) = u;
        }
    } else {
        // ---- fwht_x on row (blockIdx.x - 16384) ----
        const int g = t;
        const int row = blockIdx.x - 16384;
        const float* xr = x + (size_t)row * N_DIM;
        float v[16];

#pragma unroll
        for (int j = 0; j < 16; j++) {
            int e = g + 256 * j;
            v[j] = xr[e] * SV[e];
        }
        fwht16(v);
#pragma unroll
        for (int j = 0; j < 16; j++) s[skew(g + 256 * j)] = v[j];
        __syncthreads();

        {
            int base = (g & 15) + (g >> 4) * 256;
#pragma unroll
            for (int j = 0; j < 16; j++) v[j] = s[skew(base + 16 * j)];
            fwht16(v);
#pragma unroll
            for (int j = 0; j < 16; j++) s[skew(base + 16 * j)] = v[j];
        }
        __syncthreads();

        {
            const float sc = 1.0f / sqrtf((float)N_DIM);
#pragma unroll
            for (int j = 0; j < 16; j++) v[j] = s[skew(16 * g + j)];
            fwht16(v);
            __half2 h[8];
#pragma unroll
            for (int j = 0; j < 8; j++)
                h[j] = __floats2half2_rn(v[2 * j] * sc, v[2 * j + 1] * sc);
            uint4* dst = reinterpret_cast<uint4*>(tbuf + (size_t)row * N_DIM + 16 * g);
            dst[0] = *reinterpret_cast<uint4*>(&h[0]);
            dst[1] = *reinterpret_cast<uint4*>(&h[4]);
        }
    }
}

// ---------------------------------------------------------------------------
// K2: W-transform pass 2 on 128x32 tiles: FWHT-128 over OUTER m-index a,
//     scale by SU[m]/sqrt(M), write fp16 W'.
// ---------------------------------------------------------------------------
__global__ void __launch_bounds__(256)
hadW_pass2(const __half* __restrict__ in, const float* __restrict__ SU,
           __half* __restrict__ W)
{
    extern __shared__ float s[];
    const int b    = blockIdx.x >> 7;     // inner m-index (0..127)
    const int kt32 = blockIdx.x & 127;    // 32-col tile (0..127)
    const int t    = threadIdx.x;

    const __half* base = in + (size_t)b * N_DIM + (size_t)kt32 * 32;
#pragma unroll
    for (int q = 0; q < 2; q++) {
        int chunk = t + q * 256;          // 0..511
        int a = chunk >> 2;               // outer index = smem row
        int c8 = (chunk & 3) * 8;
        uint4 u = *reinterpret_cast<const uint4*>(base + (size_t)a * 128 * N_DIM + c8);
        const __half2* hp = reinterpret_cast<const __half2*>(&u);
        float* sp = s + a * W_COLS + c8;
#pragma unroll
        for (int j = 0; j < 4; j++) {
            float2 f = __half22float2(hp[j]);
            sp[2 * j] = f.x; sp[2 * j + 1] = f.y;
        }
    }
    __syncthreads();

    fwht128_rows(s, t);

    const float inv_m = 1.0f / 128.0f;    // 1/sqrt(16384)
    __half* ob = W + (size_t)b * N_DIM + (size_t)kt32 * 32;
#pragma unroll
    for (int q = 0; q < 2; q++) {
        int chunk = t + q * 256;          // 0..511
        int a = chunk >> 2;
        int c8 = (chunk & 3) * 8;
        float sc = __ldg(&SU[a * 128 + b]) * inv_m;
        float* sp = s + a * W_COLS + c8;
        __half2 h0 = __floats2half2_rn(sp[0] * sc, sp[1] * sc);
        __half2 h1 = __floats2half2_rn(sp[2] * sc, sp[3] * sc);
        __half2 h2 = __floats2half2_rn(sp[4] * sc, sp[5] * sc);
        __half2 h3 = __floats2half2_rn(sp[6] * sc, sp[7] * sc);
        uint4 u;
        u.x = *reinterpret_cast<unsigned*>(&h0);
        u.y = *reinterpret_cast<unsigned*>(&h1);
        u.z = *reinterpret_cast<unsigned*>(&h2);
        u.w = *reinterpret_cast<unsigned*>(&h3);
        *reinterpret_cast<uint4*>(ob + (size_t)a * 128 * N_DIM + c8) = u;
    }
}

// ---------------------------------------------------------------------------
// K3: GEMM y[T,M] = (t @ W'^T) * Wscale, fp32 out. Block 128x128x64,
//     warp tile 64x32, 3-stage cp.async (96 KB smem -> 2 CTAs/SM).
//     kc mainloop unrolled x3 so stage indices are compile-time constants.
// ---------------------------------------------------------------------------
#define BM 128
#define BN 128
#define BK 64
#define STAGES 3
#define NKC (N_DIM / BK)   // 64

__global__ void __launch_bounds__(256, 2)
gemm_mma_kernel(const __half* __restrict__ A, const __half* __restrict__ B,
                float* __restrict__ C, const float* __restrict__ Wscale_p)
{
    extern __shared__ uint4 smem4[];
    const uint32_t sbase = smem_u32(smem4);

    const int tid = threadIdx.x;
    const int wid = tid >> 5;
    const int lane = tid & 31;
    const int bm = blockIdx.x * BM;   // T dimension (A L2-resident)
    const int bn = blockIdx.y * BN;   // M dimension

    const int wm = (wid >> 2) * 64;
    const int wn = (wid & 3) * 32;

    float acc[4][4][4];
#pragma unroll
    for (int i = 0; i < 4; i++)
#pragma unroll
        for (int j = 0; j < 4; j++)
#pragma unroll
            for (int q = 0; q < 4; q++) acc[i][j][q] = 0.0f;

    const int lrow = tid >> 3;
    const int lc = tid & 7;
    const __half* Ab = A + (size_t)bm * N_DIM + lc * 8;
    const __half* Bb = B + (size_t)bn * N_DIM + lc * 8;

    auto issue_stage = [&](int kc, int st) {
        const __half* Ag = Ab + kc * BK;
        const __half* Bg = Bb + kc * BK;
#pragma unroll
        for (int p = 0; p < 4; p++) {
            int r = lrow + p * 32;
            int cc = lc ^ (r & 7);
            uint32_t da = sbase + ((st * 1024 + r * 8 + cc) << 4);
            uint32_t db = sbase + (((STAGES + st) * 1024 + r * 8 + cc) << 4);
            cp16(da, Ag + (size_t)r * N_DIM);
            cp16(db, Bg + (size_t)r * N_DIM);
        }
        CP_COMMIT();
    };

    issue_stage(0, 0);
    issue_stage(1, 1);

    const int ra = wm + (lane & 15);
    const int ca = (lane >> 4);
    const int rb = wn + (lane & 7) + ((lane & 16) ? 8 : 0);
    const int cb = (lane >> 3) & 1;

#pragma unroll 3
    for (int kc = 0; kc < NKC; kc++) {
        CP_WAIT(1);
        __syncthreads();

        if (kc + 2 < NKC) issue_stage(kc + 2, (kc + 2) % STAGES);
        else CP_COMMIT();

        const int st = kc % STAGES;
        const uint32_t abase = sbase + ((st * 1024) << 4);
        const uint32_t bbase = sbase + (((STAGES + st) * 1024) << 4);

#pragma unroll
        for (int kk = 0; kk < 4; kk++) {
            uint32_t a[4][4];
            uint32_t b[4][2];
#pragma unroll
            for (int mi = 0; mi < 4; mi++) {
                int r = ra + mi * 16;
                int c = (kk * 2 + ca) ^ (r & 7);
                LDSM4(a[mi][0], a[mi][1], a[mi][2], a[mi][3],
                      abase + ((r * 8 + c) << 4));
            }
#pragma unroll
            for (int njp = 0; njp < 2; njp++) {
                int r = rb + njp * 16;
                int c = (kk * 2 + cb) ^ (r & 7);
                uint32_t t0, t1, t2, t3;
                LDSM4(t0, t1, t2, t3, bbase + ((r * 8 + c) << 4));
                b[njp * 2 + 0][0] = t0;  b[njp * 2 + 0][1] = t1;
                b[njp * 2 + 1][0] = t2;  b[njp * 2 + 1][1] = t3;
            }
#pragma unroll
            for (int mi = 0; mi < 4; mi++)
#pragma unroll
                for (int nj = 0; nj < 4; nj++)
                    MMA16816(acc[mi][nj], a[mi], b[nj]);
        }
    }

    // epilogue: fp32 stores scaled by Wscale
    const float ws = __ldg(Wscale_p);
    const int er = lane >> 2;
    const int ec = (lane & 3) * 2;
#pragma unroll
    for (int mi = 0; mi < 4; mi++) {
#pragma unroll
        for (int nj = 0; nj < 4; nj++) {
            size_t r0 = (size_t)(bm + wm + mi * 16 + er) * M_DIM + (bn + wn + nj * 8 + ec);
            size_t r1 = r0 + (size_t)8 * M_DIM;
            __stcs(reinterpret_cast<float2*>(C + r0),
                   make_float2(acc[mi][nj][0] * ws, acc[mi][nj][1] * ws));
            __stcs(reinterpret_cast<float2*>(C + r1),
                   make_float2(acc[mi][nj][2] * ws, acc[mi][nj][3] * ws));
        }
    }
}

// ---------------------------------------------------------------------------
// Launch
// ---------------------------------------------------------------------------
extern "C" void kernel_launch(void* const* d_in, const int* in_sizes, int n_in,
                              void* d_out, int out_size)
{
    const float* x   = (const float*)d_in[0];
    const int*   Q1  = (const int*)d_in[1];
    const int*   Q2  = (const int*)d_in[2];
    const float* SU  = (const float*)d_in[3];
    const float* SV  = (const float*)d_in[4];
    const float* cb1 = (const float*)d_in[5];
    const float* cb2 = (const float*)d_in[6];
    const float* Wsc = (const float*)d_in[7];
    const float* irs = (const float*)d_in[8];
    float* out = (float*)d_out;

    __half *t_p, *W_p, *Wi_p;
    cudaGetSymbolAddress((void**)&t_p, g_t);
    cudaGetSymbolAddress((void**)&W_p, g_W);
    cudaGetSymbolAddress((void**)&Wi_p, g_Wi);

    // K1: fused [decode + inner-m FWHT tiles] + [fwht_x rows]
    int psmem = (4096 + 256) * (int)sizeof(float);
    cudaFuncSetAttribute(k1_dispatch, cudaFuncAttributeMaxDynamicSharedMemorySize, psmem);
    cudaFuncSetAttribute(hadW_pass2, cudaFuncAttributeMaxDynamicSharedMemorySize, psmem);
    k1_dispatch<<<16384 + 8192, 256, psmem>>>(Q1, Q2, cb1, cb2, irs, Wi_p, x, SV, t_p);

    // K2: outer-m FWHT + SU scale (128x32 tiles)
    hadW_pass2<<<16384, 256, 128 * W_COLS * (int)sizeof(float)>>>(Wi_p, SU, W_p);

    // K3: GEMM directly into d_out (fp32, scaled by Wscale)
    int gemm_smem = 2 * STAGES * 128 * 8 * (int)sizeof(uint4);
    cudaFuncSetAttribute(gemm_mma_kernel,
                         cudaFuncAttributeMaxDynamicSharedMemorySize, gemm_smem);
    dim3 grid(T_DIM / BM, M_DIM / BN);
    gemm_mma_kernel<<<grid, 256, gemm_smem>>>(t_p, W_p, out, Wsc);
}